// round 1
// baseline (speedup 1.0000x reference)
#include <cuda_runtime.h>
#include <math.h>

#define BATCH 4
#define CCH   512
#define HW    4096

// ---------------- scratch (static __device__ — no allocation allowed) -------
__device__ float g_mean_cc[BATCH*CCH];
__device__ float g_inv_cc [BATCH*CCH];
__device__ float g_mean_ss[BATCH*CCH];
__device__ float g_inv_ss [BATCH*CCH];
__device__ float g_W1p[BATCH*CCH*CCH];
__device__ float g_b1p[BATCH*CCH];
__device__ float g_W2p[BATCH*CCH*CCH];
__device__ float g_b2p[BATCH*CCH];
__device__ float g_Q[(size_t)BATCH*HW*CCH];   // (b, pos, ch)
__device__ float g_K[(size_t)BATCH*HW*CCH];
__device__ float g_V[(size_t)BATCH*HW*CCH];
__device__ float g_O[(size_t)BATCH*HW*CCH];
__device__ float g_S[(size_t)BATCH*HW*HW];    // scores / softmax, 256 MB

// ---------------- reductions -------------------------------------------------
__device__ __forceinline__ float warpSum(float v) {
    #pragma unroll
    for (int o = 16; o > 0; o >>= 1) v += __shfl_down_sync(0xffffffffu, v, o);
    return v;
}
__device__ __forceinline__ float warpMax(float v) {
    #pragma unroll
    for (int o = 16; o > 0; o >>= 1) v = fmaxf(v, __shfl_down_sync(0xffffffffu, v, o));
    return v;
}

// ---------------- instance-norm stats ---------------------------------------
// one block per (b,c) row; unbiased variance (ddof=1) to match torch/jax ref
__global__ __launch_bounds__(256) void stats_kernel(
    const float* __restrict__ x, float* __restrict__ mean, float* __restrict__ inv)
{
    int row = blockIdx.x;                      // 0..BATCH*CCH-1
    const float* p = x + (size_t)row * HW;
    float s = 0.f, sq = 0.f;
    for (int i = threadIdx.x; i < HW; i += 256) {
        float v = p[i];
        s += v; sq += v * v;
    }
    s  = warpSum(s);
    sq = warpSum(sq);
    __shared__ float ss[8], ssq[8];
    int w = threadIdx.x >> 5, lane = threadIdx.x & 31;
    if (lane == 0) { ss[w] = s; ssq[w] = sq; }
    __syncthreads();
    if (threadIdx.x == 0) {
        float S = 0.f, SQ = 0.f;
        #pragma unroll
        for (int i = 0; i < 8; i++) { S += ss[i]; SQ += ssq[i]; }
        float m   = S / (float)HW;
        float var = (SQ - (float)HW * m * m) / (float)(HW - 1);
        mean[row] = m;
        inv[row]  = rsqrtf(var + 1e-5f);
    }
}

// ---------------- fold instance-norm into conv weights ----------------------
// W'[b][o][c] = W[o][c]*inv[b][c];  b'[b][o] = b[o] - sum_c W[o][c]*mean[b][c]*inv[b][c]
__global__ __launch_bounds__(128) void fold_kernel(
    const float* __restrict__ W, const float* __restrict__ bias,
    const float* __restrict__ mean, const float* __restrict__ inv,
    float* __restrict__ Wp, float* __restrict__ bp)
{
    int o = blockIdx.x, b = blockIdx.y;
    const float* mr = mean + b * CCH;
    const float* ir = inv  + b * CCH;
    float part = 0.f;
    for (int c = threadIdx.x; c < CCH; c += 128) {
        float w  = W[o * CCH + c];
        float iv = ir[c];
        Wp[((size_t)b * CCH + o) * CCH + c] = w * iv;
        part += w * mr[c] * iv;
    }
    part = warpSum(part);
    __shared__ float sp[4];
    int w = threadIdx.x >> 5, lane = threadIdx.x & 31;
    if (lane == 0) sp[w] = part;
    __syncthreads();
    if (threadIdx.x == 0)
        bp[b * CCH + o] = bias[o] - (sp[0] + sp[1] + sp[2] + sp[3]);
}

// ---------------- GEMM tiles: 64x64x16, 256 thr, 4x4 per thread -------------
// Q/K/V:  Out[p][o] = sum_c W[o][c] * X[c][p] + bias[o]
__global__ __launch_bounds__(256) void gemm_qkv(
    const float* __restrict__ X, const float* __restrict__ W,
    const float* __restrict__ bias, float* __restrict__ Out,
    int wStride, int bStride)
{
    int b = blockIdx.z;
    X    += (size_t)b * CCH * HW;
    W    += (size_t)b * wStride;
    bias += (size_t)b * bStride;
    Out  += (size_t)b * HW * CCH;
    int m0 = blockIdx.x * 64;          // position
    int n0 = blockIdx.y * 64;          // out channel
    __shared__ float Xs[16][68];
    __shared__ float Ws[16][68];
    int tid = threadIdx.x;
    int tx = tid & 15, ty = tid >> 4;
    int xk = tid >> 4, xm = (tid & 15) * 4;     // natural load of X (p contiguous)
    int wn = tid >> 2, wk = (tid & 3) * 4;      // transpose load of W (c contiguous)
    float acc[4][4] = {};
    for (int kt = 0; kt < CCH; kt += 16) {
        float4 xv = *reinterpret_cast<const float4*>(X + (size_t)(kt + xk) * HW + m0 + xm);
        float4 wv = *reinterpret_cast<const float4*>(W + (size_t)(n0 + wn) * CCH + kt + wk);
        *reinterpret_cast<float4*>(&Xs[xk][xm]) = xv;
        Ws[wk + 0][wn] = wv.x; Ws[wk + 1][wn] = wv.y;
        Ws[wk + 2][wn] = wv.z; Ws[wk + 3][wn] = wv.w;
        __syncthreads();
        #pragma unroll
        for (int kk = 0; kk < 16; kk++) {
            float4 rm = *reinterpret_cast<float4*>(&Xs[kk][ty * 4]);
            float4 rn = *reinterpret_cast<float4*>(&Ws[kk][tx * 4]);
            float m_[4] = {rm.x, rm.y, rm.z, rm.w};
            float n_[4] = {rn.x, rn.y, rn.z, rn.w};
            #pragma unroll
            for (int i = 0; i < 4; i++)
                #pragma unroll
                for (int j = 0; j < 4; j++) acc[i][j] += m_[i] * n_[j];
        }
        __syncthreads();
    }
    float4 bv = *reinterpret_cast<const float4*>(bias + n0 + tx * 4);
    #pragma unroll
    for (int i = 0; i < 4; i++) {
        int m = m0 + ty * 4 + i;
        float4 o = make_float4(acc[i][0] + bv.x, acc[i][1] + bv.y,
                               acc[i][2] + bv.z, acc[i][3] + bv.w);
        *reinterpret_cast<float4*>(Out + (size_t)m * CCH + n0 + tx * 4) = o;
    }
}

// scores: S[q][k] = sum_c Q[q][c]*K[k][c]   (NT, M=N=4096, K=512)
__global__ __launch_bounds__(256) void gemm_scores(
    const float* __restrict__ Q, const float* __restrict__ K, float* __restrict__ S)
{
    int b = blockIdx.z;
    Q += (size_t)b * HW * CCH;
    K += (size_t)b * HW * CCH;
    S += (size_t)b * HW * HW;
    int m0 = blockIdx.x * 64;
    int n0 = blockIdx.y * 64;
    __shared__ float As[16][68];
    __shared__ float Bs[16][68];
    int tid = threadIdx.x;
    int tx = tid & 15, ty = tid >> 4;
    int am = tid >> 2, ak = (tid & 3) * 4;
    float acc[4][4] = {};
    for (int kt = 0; kt < CCH; kt += 16) {
        float4 av = *reinterpret_cast<const float4*>(Q + (size_t)(m0 + am) * CCH + kt + ak);
        float4 bv = *reinterpret_cast<const float4*>(K + (size_t)(n0 + am) * CCH + kt + ak);
        As[ak + 0][am] = av.x; As[ak + 1][am] = av.y; As[ak + 2][am] = av.z; As[ak + 3][am] = av.w;
        Bs[ak + 0][am] = bv.x; Bs[ak + 1][am] = bv.y; Bs[ak + 2][am] = bv.z; Bs[ak + 3][am] = bv.w;
        __syncthreads();
        #pragma unroll
        for (int kk = 0; kk < 16; kk++) {
            float4 rm = *reinterpret_cast<float4*>(&As[kk][ty * 4]);
            float4 rn = *reinterpret_cast<float4*>(&Bs[kk][tx * 4]);
            float m_[4] = {rm.x, rm.y, rm.z, rm.w};
            float n_[4] = {rn.x, rn.y, rn.z, rn.w};
            #pragma unroll
            for (int i = 0; i < 4; i++)
                #pragma unroll
                for (int j = 0; j < 4; j++) acc[i][j] += m_[i] * n_[j];
        }
        __syncthreads();
    }
    #pragma unroll
    for (int i = 0; i < 4; i++) {
        int m = m0 + ty * 4 + i;
        float4 o = make_float4(acc[i][0], acc[i][1], acc[i][2], acc[i][3]);
        *reinterpret_cast<float4*>(S + (size_t)m * HW + n0 + tx * 4) = o;
    }
}

// softmax over last dim, in place; one block per row, 16 values per thread in regs
__global__ __launch_bounds__(256) void softmax_kernel(float* __restrict__ S)
{
    float* p = S + (size_t)blockIdx.x * HW;
    int tid = threadIdx.x;
    float vals[16];
    float mx = -INFINITY;
    #pragma unroll
    for (int i = 0; i < 16; i++) {
        vals[i] = p[tid + i * 256];
        mx = fmaxf(mx, vals[i]);
    }
    __shared__ float sh[8];
    int w = tid >> 5, lane = tid & 31;
    mx = warpMax(mx);
    if (lane == 0) sh[w] = mx;
    __syncthreads();
    if (w == 0) {
        float v = (lane < 8) ? sh[lane] : -INFINITY;
        v = warpMax(v);
        if (lane == 0) sh[0] = v;
    }
    __syncthreads();
    mx = sh[0];
    __syncthreads();
    float s = 0.f;
    #pragma unroll
    for (int i = 0; i < 16; i++) {
        vals[i] = expf(vals[i] - mx);
        s += vals[i];
    }
    s = warpSum(s);
    if (lane == 0) sh[w] = s;
    __syncthreads();
    if (w == 0) {
        float v = (lane < 8) ? sh[lane] : 0.f;
        v = warpSum(v);
        if (lane == 0) sh[0] = v;
    }
    __syncthreads();
    float invs = 1.f / sh[0];
    #pragma unroll
    for (int i = 0; i < 16; i++) p[tid + i * 256] = vals[i] * invs;
}

// O[q][c] = sum_k A[q][k] * V[k][c]   (NN, M=4096, N=512, K=4096)
__global__ __launch_bounds__(256) void gemm_av(
    const float* __restrict__ A, const float* __restrict__ V, float* __restrict__ O)
{
    int b = blockIdx.z;
    A += (size_t)b * HW * HW;
    V += (size_t)b * HW * CCH;
    O += (size_t)b * HW * CCH;
    int m0 = blockIdx.x * 64;
    int n0 = blockIdx.y * 64;
    __shared__ float As[16][68];
    __shared__ float Bs[16][68];
    int tid = threadIdx.x;
    int tx = tid & 15, ty = tid >> 4;
    int am = tid >> 2, ak = (tid & 3) * 4;      // transpose load of A
    int bk = tid >> 4, bn = (tid & 15) * 4;     // natural load of V
    float acc[4][4] = {};
    for (int kt = 0; kt < HW; kt += 16) {
        float4 av = *reinterpret_cast<const float4*>(A + (size_t)(m0 + am) * HW + kt + ak);
        float4 bv = *reinterpret_cast<const float4*>(V + (size_t)(kt + bk) * CCH + n0 + bn);
        As[ak + 0][am] = av.x; As[ak + 1][am] = av.y; As[ak + 2][am] = av.z; As[ak + 3][am] = av.w;
        *reinterpret_cast<float4*>(&Bs[bk][bn]) = bv;
        __syncthreads();
        #pragma unroll
        for (int kk = 0; kk < 16; kk++) {
            float4 rm = *reinterpret_cast<float4*>(&As[kk][ty * 4]);
            float4 rn = *reinterpret_cast<float4*>(&Bs[kk][tx * 4]);
            float m_[4] = {rm.x, rm.y, rm.z, rm.w};
            float n_[4] = {rn.x, rn.y, rn.z, rn.w};
            #pragma unroll
            for (int i = 0; i < 4; i++)
                #pragma unroll
                for (int j = 0; j < 4; j++) acc[i][j] += m_[i] * n_[j];
        }
        __syncthreads();
    }
    #pragma unroll
    for (int i = 0; i < 4; i++) {
        int m = m0 + ty * 4 + i;
        float4 o = make_float4(acc[i][0], acc[i][1], acc[i][2], acc[i][3]);
        *reinterpret_cast<float4*>(O + (size_t)m * CCH + n0 + tx * 4) = o;
    }
}

// out[o][p] = sum_c Wrs[o][c]*O[p][c] + brs[o] + x_fcc[o][p]  (NT, M=512, N=4096, K=512)
__global__ __launch_bounds__(256) void gemm_final(
    const float* __restrict__ Wrs, const float* __restrict__ brs,
    const float* __restrict__ O, const float* __restrict__ xfcc, float* __restrict__ out)
{
    int b = blockIdx.z;
    O    += (size_t)b * HW * CCH;
    xfcc += (size_t)b * CCH * HW;
    out  += (size_t)b * CCH * HW;
    int n0 = blockIdx.x * 64;      // position
    int m0 = blockIdx.y * 64;      // out channel
    __shared__ float As[16][68];
    __shared__ float Bs[16][68];
    int tid = threadIdx.x;
    int tx = tid & 15, ty = tid >> 4;
    int am = tid >> 2, ak = (tid & 3) * 4;
    float acc[4][4] = {};
    for (int kt = 0; kt < CCH; kt += 16) {
        float4 av = *reinterpret_cast<const float4*>(Wrs + (size_t)(m0 + am) * CCH + kt + ak);
        float4 bv = *reinterpret_cast<const float4*>(O   + (size_t)(n0 + am) * CCH + kt + ak);
        As[ak + 0][am] = av.x; As[ak + 1][am] = av.y; As[ak + 2][am] = av.z; As[ak + 3][am] = av.w;
        Bs[ak + 0][am] = bv.x; Bs[ak + 1][am] = bv.y; Bs[ak + 2][am] = bv.z; Bs[ak + 3][am] = bv.w;
        __syncthreads();
        #pragma unroll
        for (int kk = 0; kk < 16; kk++) {
            float4 rm = *reinterpret_cast<float4*>(&As[kk][ty * 4]);
            float4 rn = *reinterpret_cast<float4*>(&Bs[kk][tx * 4]);
            float m_[4] = {rm.x, rm.y, rm.z, rm.w};
            float n_[4] = {rn.x, rn.y, rn.z, rn.w};
            #pragma unroll
            for (int i = 0; i < 4; i++)
                #pragma unroll
                for (int j = 0; j < 4; j++) acc[i][j] += m_[i] * n_[j];
        }
        __syncthreads();
    }
    #pragma unroll
    for (int i = 0; i < 4; i++) {
        int m = m0 + ty * 4 + i;
        float bm = brs[m];
        float4 res = *reinterpret_cast<const float4*>(xfcc + (size_t)m * HW + n0 + tx * 4);
        float4 o = make_float4(acc[i][0] + bm + res.x, acc[i][1] + bm + res.y,
                               acc[i][2] + bm + res.z, acc[i][3] + bm + res.w);
        *reinterpret_cast<float4*>(out + (size_t)m * HW + n0 + tx * 4) = o;
    }
}

// ---------------- launch -----------------------------------------------------
extern "C" void kernel_launch(void* const* d_in, const int* in_sizes, int n_in,
                              void* d_out, int out_size)
{
    const float* x_fcc = (const float*)d_in[0];
    const float* x_fss = (const float*)d_in[1];
    const float* w1    = (const float*)d_in[2];
    const float* b1    = (const float*)d_in[3];
    const float* w2    = (const float*)d_in[4];
    const float* b2    = (const float*)d_in[5];
    const float* w3    = (const float*)d_in[6];
    const float* b3    = (const float*)d_in[7];
    const float* wrs   = (const float*)d_in[8];
    const float* brs   = (const float*)d_in[9];
    float* out = (float*)d_out;

    float *pMcc, *pIcc, *pMss, *pIss, *pW1p, *pB1p, *pW2p, *pB2p;
    float *pQ, *pK, *pV, *pO, *pS;
    cudaGetSymbolAddress((void**)&pMcc, g_mean_cc);
    cudaGetSymbolAddress((void**)&pIcc, g_inv_cc);
    cudaGetSymbolAddress((void**)&pMss, g_mean_ss);
    cudaGetSymbolAddress((void**)&pIss, g_inv_ss);
    cudaGetSymbolAddress((void**)&pW1p, g_W1p);
    cudaGetSymbolAddress((void**)&pB1p, g_b1p);
    cudaGetSymbolAddress((void**)&pW2p, g_W2p);
    cudaGetSymbolAddress((void**)&pB2p, g_b2p);
    cudaGetSymbolAddress((void**)&pQ, g_Q);
    cudaGetSymbolAddress((void**)&pK, g_K);
    cudaGetSymbolAddress((void**)&pV, g_V);
    cudaGetSymbolAddress((void**)&pO, g_O);
    cudaGetSymbolAddress((void**)&pS, g_S);

    // 1) instance-norm stats for both inputs
    stats_kernel<<<BATCH * CCH, 256>>>(x_fcc, pMcc, pIcc);
    stats_kernel<<<BATCH * CCH, 256>>>(x_fss, pMss, pIss);

    // 2) fold norm into conv weights (per batch)
    fold_kernel<<<dim3(CCH, BATCH), 128>>>(w1, b1, pMcc, pIcc, pW1p, pB1p);
    fold_kernel<<<dim3(CCH, BATCH), 128>>>(w2, b2, pMss, pIss, pW2p, pB2p);

    // 3) Q, K, V projections -> (pos, ch) layout
    gemm_qkv<<<dim3(64, 8, BATCH), 256>>>(x_fcc, pW1p, pB1p, pQ, CCH * CCH, CCH);
    gemm_qkv<<<dim3(64, 8, BATCH), 256>>>(x_fss, pW2p, pB2p, pK, CCH * CCH, CCH);
    gemm_qkv<<<dim3(64, 8, BATCH), 256>>>(x_fss, w3,   b3,   pV, 0, 0);

    // 4) scores = Q K^T
    gemm_scores<<<dim3(64, 64, BATCH), 256>>>(pQ, pK, pS);

    // 5) softmax rows (in place)
    softmax_kernel<<<BATCH * HW, 256>>>(pS);

    // 6) O = A V
    gemm_av<<<dim3(64, 8, BATCH), 256>>>(pS, pV, pO);

    // 7) final conv + bias + residual
    gemm_final<<<dim3(64, 8, BATCH), 256>>>(wrs, brs, pO, x_fcc, out);
}